// round 13
// baseline (speedup 1.0000x reference)
#include <cuda_runtime.h>

// SSIM loss — vertical-first separable streaming.
// Each thread owns one staged column: LDG -> (s,d)=(x+y,x-y) -> squares once
// -> 11-slot vertical ring in registers (packed f32x2). Completed v-rows go
// to smem (STS.128); horizontal 11-tap stage (LDS.128 + packed fma) directly
// yields final windowed moments (no second ring). All math fp32.
// 16x3x512x512 fp32 pred/target -> scalar 1 - mean(ssim_map).

#define IMG   512
#define PLANES 48
#define KW    11
#define KR    5
#define TW    128                // output tile width
#define TH    64                 // output tile height
#define SW    (TW + 2*KR)        // 138 staged columns
#define NROWS (TH + 2*KR)        // 74 input rows streamed
#define NTHREADS 160             // 5 warps; threads 0..137 own columns
#define GRIDX (IMG/TW)           // 4
#define GRIDY (IMG/TH)           // 8
#define NBLK  (GRIDX*GRIDY*PLANES)  // 1536
#define NPIXD ((double)PLANES * IMG * IMG)

typedef unsigned long long u64;

__device__ double       g_sum;
__device__ unsigned int g_cnt;

__device__ __forceinline__ u64 pk2(float x, float y) {
    u64 r; asm("mov.b64 %0, {%1, %2};" : "=l"(r) : "f"(x), "f"(y)); return r;
}
__device__ __forceinline__ void upk2(u64 v, float& x, float& y) {
    asm("mov.b64 {%0, %1}, %2;" : "=f"(x), "=f"(y) : "l"(v));
}
__device__ __forceinline__ u64 fma2(u64 a, u64 b, u64 c) {
    u64 d; asm("fma.rn.f32x2 %0, %1, %2, %3;" : "=l"(d) : "l"(a), "l"(b), "l"(c));
    return d;
}
__device__ __forceinline__ u64 mul2(u64 a, u64 b) {
    u64 d; asm("mul.rn.f32x2 %0, %1, %2;" : "=l"(d) : "l"(a), "l"(b));
    return d;
}

__global__ __launch_bounds__(NTHREADS, 4)
void ssim_kernel(const float* __restrict__ pred,
                 const float* __restrict__ targ,
                 float* __restrict__ out)
{
    constexpr float W[KW] = {
        0.00102838f, 0.00759876f, 0.03600077f, 0.10936069f, 0.21300554f,
        0.26601173f,
        0.21300554f, 0.10936069f, 0.03600077f, 0.00759876f, 0.00102838f
    };
    constexpr float C1 = 0.0001f;
    constexpr float C2 = 0.0009f;

    // double-buffered v-rows: (vmu_s, vmu_d, vsq_s, vsq_d) per column
    __shared__ float4 vbuf[2][SW];
    __shared__ float  wsum[NTHREADS / 32];

    const int t  = threadIdx.x;
    const int x0 = blockIdx.x * TW;
    const int y0 = blockIdx.y * TH;
    const float* __restrict__ xin = pred + (size_t)blockIdx.z * IMG * IMG;
    const float* __restrict__ yin = targ + (size_t)blockIdx.z * IMG * IMG;

    const int  gx  = x0 - KR + t;           // this thread's staged column
    const bool cok = (t < SW);

    auto ldrow = [&](int j, float& ax, float& ay) {
        const int  gy = y0 - KR + j;
        const bool ok = cok && (gy >= 0) && (gy < IMG) && (gx >= 0) && (gx < IMG);
        const long b  = (long)gy * IMG;
        ax = ok ? xin[b + gx] : 0.0f;
        ay = ok ? yin[b + gx] : 0.0f;
    };

    // 6 distinct packed weights (Gaussian symmetry)
    u64 WW[6];
    #pragma unroll
    for (int k = 0; k < 6; ++k) WW[k] = pk2(W[k], W[k]);
    const u64 NEG1 = pk2(-1.0f, -1.0f);
    const u64 Z64  = 0ull;

    // vertical ring accumulators: packed (mu_s,mu_d), (E[s^2],E[d^2])
    u64 aMU[11], aSQ[11];
    #pragma unroll
    for (int s = 0; s < 11; ++s) { aMU[s] = Z64; aSQ[s] = Z64; }

    float tsum = 0.0f;

    float cx, cy;            // current input row value for this column
    ldrow(0, cx, cy);

    // rows j = 0..73 (74 = 6*11 + 8)
    for (int jb = 0; jb < 7; ++jb) {
        #pragma unroll
        for (int u = 0; u < 11; ++u) {
            if (jb == 6 && u >= 8) break;     // uniform epilogue cut
            const int j = jb * 11 + u;

            // prefetch next row (register-resident, overlaps compute)
            float nx_, ny_;
            ldrow(j + 1, nx_, ny_);

            // transform once: (s,d) and squares
            const u64 p  = pk2(cx + cy, cx - cy);
            const u64 pp = mul2(p, p);

            // ---- vertical ring update: 2 packed fma per tap ----
            #pragma unroll
            for (int q = 0; q < KW; ++q) {
                const int ss = (u - q + 11) % 11;     // literal
                const int pw = (q < 6) ? q : 10 - q;  // literal
                aMU[ss] = fma2(WW[pw], p,  aMU[ss]);
                aSQ[ss] = fma2(WW[pw], pp, aSQ[ss]);
            }

            // ---- v-row o = j-10 complete: publish to smem ----
            const int so = (u + 1) % 11;              // literal
            const int o  = j - (KW - 1);
            const int ob = (jb ^ u) & 1;              // == o & 1 for o >= 0
            if (o >= 0 && cok) {
                float m0, m1, q0, q1;
                upk2(aMU[so], m0, m1);
                upk2(aSQ[so], q0, q1);
                vbuf[ob][t] = make_float4(m0, m1, q0, q1);
            }
            aMU[so] = Z64; aSQ[so] = Z64;
            __syncthreads();

            // ---- horizontal stage: final moments + SSIM for row o ----
            if (o >= 0 && t < TW) {
                const float4* vb = vbuf[ob];
                u64 hmu = Z64, hsq = Z64;
                #pragma unroll
                for (int k = 0; k < KW; ++k) {
                    const int kw = (k < 6) ? k : 10 - k;   // literal
                    const float4 f = vb[t + k];            // LDS.128
                    hmu = fma2(WW[kw], pk2(f.x, f.y), hmu);
                    hsq = fma2(WW[kw], pk2(f.z, f.w), hsq);
                }
                const u64 mu2 = mul2(hmu, hmu);            // (mus^2, mud^2)
                const u64 sg  = fma2(mu2, NEG1, hsq);      // (sig_s, sig_d)
                float g0, g1, v0, v1;
                upk2(mu2, g0, g1);
                upk2(sg,  v0, v1);
                // 2*mu_xy=(g0-g1)/2 ; mu_x^2+mu_y^2=(g0+g1)/2
                // 2*sg_xy=(v0-v1)/2 ; sg_x+sg_y    =(v0+v1)/2
                const float num = (0.5f*(g0 - g1) + C1) * (0.5f*(v0 - v1) + C2);
                const float den = (0.5f*(g0 + g1) + C1) * (0.5f*(v0 + v1) + C2);
                tsum += __fdividef(num, den);
            }

            cx = nx_;  cy = ny_;
            // buffer reuse safety: vbuf[ob] written at iter o is read after
            // BAR_o and strictly before BAR_{o+1}; the next write to the same
            // buffer (iter o+2) happens after BAR_{o+1}.
        }
    }

    // ---- reduction: warp -> block -> global ----
    #pragma unroll
    for (int off = 16; off > 0; off >>= 1)
        tsum += __shfl_down_sync(0xffffffffu, tsum, off);
    if ((t & 31) == 0) wsum[t >> 5] = tsum;
    __syncthreads();

    if (t == 0) {
        double bs = 0.0;
        #pragma unroll
        for (int wq = 0; wq < NTHREADS / 32; ++wq) bs += (double)wsum[wq];
        atomicAdd(&g_sum, bs);
        __threadfence();
        const unsigned r = atomicAdd(&g_cnt, 1u);
        if (r == NBLK - 1u) {
            const double sall = g_sum;
            out[0] = (float)(1.0 - sall / NPIXD);
            g_sum = 0.0;
            __threadfence();
            g_cnt = 0u;
        }
    }
}

extern "C" void kernel_launch(void* const* d_in, const int* in_sizes, int n_in,
                              void* d_out, int out_size)
{
    const float* pred = (const float*)d_in[0];
    const float* targ = (const float*)d_in[1];
    float* out = (float*)d_out;

    dim3 grid(GRIDX, GRIDY, PLANES);   // 4 x 8 x 48 = 1536 blocks
    ssim_kernel<<<grid, NTHREADS>>>(pred, targ, out);
}

// round 14
// speedup vs baseline: 1.0176x; 1.0176x over previous
#include <cuda_runtime.h>

// SSIM loss, fused streaming kernel — R6 base ((s,d) transform, two packed
// f32x2 rings, double-buffered block-wide staging) + micro-opts:
//   * 0.5 factors folded out of the SSIM ratio (scale-invariant)
//   * warp-uniform row-bounds branch + block-uniform interior-x fast path
//   * single row-base index computation
// 16x3x512x512 fp32 pred/target -> scalar 1 - mean(ssim_map).

#define IMG   512
#define PLANES 48
#define KW    11
#define KR    5
#define TW    128
#define TH    64
#define NRB   7                  // 7*11 = 77 rows streamed >= TH+10
#define SW    (TW + 2*KR)        // 138
#define NTHREADS 128
#define GRIDX (IMG/TW)           // 4
#define GRIDY (IMG/TH)           // 8
#define NBLK  (GRIDX*GRIDY*PLANES)  // 1536
#define NPIXD ((double)PLANES * IMG * IMG)

typedef unsigned long long u64;

__device__ double       g_sum;
__device__ unsigned int g_cnt;

__device__ __forceinline__ u64 pk2(float x, float y) {
    u64 r; asm("mov.b64 %0, {%1, %2};" : "=l"(r) : "f"(x), "f"(y)); return r;
}
__device__ __forceinline__ void upk2(u64 v, float& x, float& y) {
    asm("mov.b64 {%0, %1}, %2;" : "=f"(x), "=f"(y) : "l"(v));
}
__device__ __forceinline__ u64 fma2(u64 a, u64 b, u64 c) {
    u64 d; asm("fma.rn.f32x2 %0, %1, %2, %3;" : "=l"(d) : "l"(a), "l"(b), "l"(c));
    return d;
}
__device__ __forceinline__ u64 mul2(u64 a, u64 b) {
    u64 d; asm("mul.rn.f32x2 %0, %1, %2;" : "=l"(d) : "l"(a), "l"(b));
    return d;
}

__global__ __launch_bounds__(NTHREADS, 5)
void ssim_kernel(const float* __restrict__ pred,
                 const float* __restrict__ targ,
                 float* __restrict__ out)
{
    constexpr float W[KW] = {
        0.00102838f, 0.00759876f, 0.03600077f, 0.10936069f, 0.21300554f,
        0.26601173f,
        0.21300554f, 0.10936069f, 0.03600077f, 0.00759876f, 0.00102838f
    };
    // folded: ratio scaled by 4 in both numerator and denominator
    constexpr float TC1 = 0.0002f;   // 2 * 0.01^2
    constexpr float TC2 = 0.0018f;   // 2 * 0.03^2

    __shared__ float2 sb[2][SW];      // interleaved (s, d) staging rows
    __shared__ float  wsum[4];

    const int t  = threadIdx.x;
    const int x0 = blockIdx.x * TW;
    const int y0 = blockIdx.y * TH;
    const float* __restrict__ xin = pred + (size_t)blockIdx.z * IMG * IMG;
    const float* __restrict__ yin = targ + (size_t)blockIdx.z * IMG * IMG;

    const int  gx0  = x0 - KR + t;
    const int  gx1  = gx0 + TW;
    const bool tail = (t < SW - TW);
    // block-uniform: every staged column of this block strictly inside [0,512)?
    // x0 in {128, 256}: gx0 in [123,379], gx1 in [251,506] (incl. tail) -> safe
    const bool safe_x = (x0 > 0) && (x0 + TW < IMG);

    // load one padded row; return (s,d) = (x+y, x-y) pairs
    auto ldrow = [&](int j, float& s0, float& d0, float& s1, float& d1) {
        const int gy = y0 - KR + j;
        float ax0 = 0.f, ay0 = 0.f, ax1 = 0.f, ay1 = 0.f;
        if (gy >= 0 && gy < IMG) {              // warp-uniform branch
            const long b = (long)gy * IMG;
            if (safe_x) {                       // block-uniform: no predicates
                ax0 = xin[b + gx0];
                ay0 = yin[b + gx0];
                if (tail) { ax1 = xin[b + gx1]; ay1 = yin[b + gx1]; }
            } else {
                const bool ok0 = (gx0 >= 0) && (gx0 < IMG);
                const bool ok1 = tail && (gx1 < IMG);
                if (ok0) { ax0 = xin[b + gx0]; ay0 = yin[b + gx0]; }
                if (ok1) { ax1 = xin[b + gx1]; ay1 = yin[b + gx1]; }
            }
        }
        s0 = ax0 + ay0;  d0 = ax0 - ay0;
        s1 = ax1 + ay1;  d1 = ax1 - ay1;
    };

    // 6 distinct packed weights (Gaussian symmetry)
    u64 WW[6];
    #pragma unroll
    for (int k = 0; k < 6; ++k) WW[k] = pk2(W[k], W[k]);
    const u64 NEG1 = pk2(-1.0f, -1.0f);
    const u64 Z64  = 0ull;

    // ring accumulators: packed (mu_s, mu_d) and (E[s^2], E[d^2])
    u64 aMU[11], aSQ[11];
    #pragma unroll
    for (int s = 0; s < 11; ++s) { aMU[s] = Z64; aSQ[s] = Z64; }

    float tsum = 0.0f;

    // preload + stage row 0
    {
        float s0, d0, s1, d1;
        ldrow(0, s0, d0, s1, d1);
        sb[0][t] = make_float2(s0, d0);
        if (tail) sb[0][TW + t] = make_float2(s1, d1);
    }
    __syncthreads();

    for (int jb = 0; jb < NRB; ++jb) {
        #pragma unroll
        for (int u = 0; u < 11; ++u) {
            const int j = jb * 11 + u;

            // prefetch next row (overlaps compute)
            float ns0, nd0, ns1, nd1;
            ldrow(j + 1, ns0, nd0, ns1, nd1);

            // ---- horizontal blur: 3 packed ops per tap ----
            const u64* s = (const u64*)sb[j & 1];
            u64 hmu = Z64, hsq = Z64;
            #pragma unroll
            for (int k = 0; k < KW; ++k) {
                const int kw = (k < 6) ? k : 10 - k;    // literal
                const u64 p  = s[t + k];                // (s, d) LDS.64
                const u64 pp = mul2(p, p);              // (s^2, d^2)
                hmu = fma2(WW[kw], p,  hmu);
                hsq = fma2(WW[kw], pp, hsq);
            }

            // ---- vertical ring update: 2 packed ops per tap ----
            #pragma unroll
            for (int p = 0; p < KW; ++p) {
                const int ss = (u - p + 11) % 11;       // literal
                const int pw = (p < 6) ? p : 10 - p;    // literal
                aMU[ss] = fma2(WW[pw], hmu, aMU[ss]);
                aSQ[ss] = fma2(WW[pw], hsq, aSQ[ss]);
            }

            // ---- finalize output row o = j-10, reset slot ----
            {
                const int so = (u + 1) % 11;
                const int o  = j - (KW - 1);
                if (o >= 0 && o < TH) {
                    const u64 mu  = aMU[so];
                    const u64 mu2 = mul2(mu, mu);             // (mus^2, mud^2)
                    const u64 sg  = fma2(mu2, NEG1, aSQ[so]); // (sig_s, sig_d)
                    float g0, g1, v0, v1;
                    upk2(mu2, g0, g1);
                    upk2(sg,  v0, v1);
                    // 4*num = ((g0-g1)+2C1)((v0-v1)+2C2); same scale on den:
                    // ratio is unchanged (scale-invariant).
                    const float num = ((g0 - g1) + TC1) * ((v0 - v1) + TC2);
                    const float den = ((g0 + g1) + TC1) * ((v0 + v1) + TC2);
                    tsum += __fdividef(num, den);
                }
                aMU[so] = Z64; aSQ[so] = Z64;
            }

            // stage prefetched row j+1 into the other buffer (overwrites data
            // last read in iter j-1, fenced by that iteration's barrier)
            const int nb = (j + 1) & 1;
            sb[nb][t] = make_float2(ns0, nd0);
            if (tail) sb[nb][TW + t] = make_float2(ns1, nd1);
            __syncthreads();
        }
    }

    // ---- reduction: warp -> block -> global ----
    #pragma unroll
    for (int off = 16; off > 0; off >>= 1)
        tsum += __shfl_down_sync(0xffffffffu, tsum, off);
    if ((t & 31) == 0) wsum[t >> 5] = tsum;
    __syncthreads();

    if (t == 0) {
        const double bs = (double)wsum[0] + (double)wsum[1]
                        + (double)wsum[2] + (double)wsum[3];
        atomicAdd(&g_sum, bs);
        __threadfence();
        const unsigned r = atomicAdd(&g_cnt, 1u);
        if (r == NBLK - 1u) {
            const double sall = g_sum;
            out[0] = (float)(1.0 - sall / NPIXD);
            g_sum = 0.0;
            __threadfence();
            g_cnt = 0u;
        }
    }
}

extern "C" void kernel_launch(void* const* d_in, const int* in_sizes, int n_in,
                              void* d_out, int out_size)
{
    const float* pred = (const float*)d_in[0];
    const float* targ = (const float*)d_in[1];
    float* out = (float*)d_out;

    dim3 grid(GRIDX, GRIDY, PLANES);   // 4 x 8 x 48 = 1536 blocks
    ssim_kernel<<<grid, NTHREADS>>>(pred, targ, out);
}

// round 15
// speedup vs baseline: 1.4833x; 1.4577x over previous
#include <cuda_runtime.h>

// SSIM loss, fused streaming kernel — best-known configuration (R6):
// (s,d)=(x+y,x-y) transform reduces SSIM to 4 convolved fields packed as two
// f32x2 rings; block-wide double-buffered staging, predicated (branch-free)
// row loads so ptxas hoists the LDGs as a deep prefetch; literal ring slots.
// Plus scale-invariant fold of the 0.5 factors in the finalize.
// 16x3x512x512 fp32 pred/target -> scalar 1 - mean(ssim_map).

#define IMG   512
#define PLANES 48
#define KW    11
#define KR    5
#define TW    128
#define TH    64
#define NRB   7                  // 7*11 = 77 rows streamed >= TH+10
#define SW    (TW + 2*KR)        // 138
#define NTHREADS 128
#define GRIDX (IMG/TW)           // 4
#define GRIDY (IMG/TH)           // 8
#define NBLK  (GRIDX*GRIDY*PLANES)  // 1536
#define NPIXD ((double)PLANES * IMG * IMG)

typedef unsigned long long u64;

__device__ double       g_sum;
__device__ unsigned int g_cnt;

__device__ __forceinline__ u64 pk2(float x, float y) {
    u64 r; asm("mov.b64 %0, {%1, %2};" : "=l"(r) : "f"(x), "f"(y)); return r;
}
__device__ __forceinline__ void upk2(u64 v, float& x, float& y) {
    asm("mov.b64 {%0, %1}, %2;" : "=f"(x), "=f"(y) : "l"(v));
}
__device__ __forceinline__ u64 fma2(u64 a, u64 b, u64 c) {
    u64 d; asm("fma.rn.f32x2 %0, %1, %2, %3;" : "=l"(d) : "l"(a), "l"(b), "l"(c));
    return d;
}
__device__ __forceinline__ u64 mul2(u64 a, u64 b) {
    u64 d; asm("mul.rn.f32x2 %0, %1, %2;" : "=l"(d) : "l"(a), "l"(b));
    return d;
}

__global__ __launch_bounds__(NTHREADS, 5)
void ssim_kernel(const float* __restrict__ pred,
                 const float* __restrict__ targ,
                 float* __restrict__ out)
{
    constexpr float W[KW] = {
        0.00102838f, 0.00759876f, 0.03600077f, 0.10936069f, 0.21300554f,
        0.26601173f,
        0.21300554f, 0.10936069f, 0.03600077f, 0.00759876f, 0.00102838f
    };
    // 0.5 factors folded out of the ratio (numerator and denominator both
    // scaled by 4; ratio unchanged): use 2*C1, 2*C2.
    constexpr float TC1 = 0.0002f;   // 2 * 0.01^2
    constexpr float TC2 = 0.0018f;   // 2 * 0.03^2

    __shared__ float2 sb[2][SW];      // interleaved (s, d) staging rows
    __shared__ float  wsum[4];

    const int t  = threadIdx.x;
    const int x0 = blockIdx.x * TW;
    const int y0 = blockIdx.y * TH;
    const float* __restrict__ xin = pred + (size_t)blockIdx.z * IMG * IMG;
    const float* __restrict__ yin = targ + (size_t)blockIdx.z * IMG * IMG;

    const int  gx0  = x0 - KR + t;
    const int  gx1  = gx0 + TW;
    const bool tail = (t < SW - TW);

    // load one padded row; PREDICATED (no branches) so the LDGs issue early
    // and their latency is covered by the row's compute. Returns (s,d).
    auto ldrow = [&](int j, float& s0, float& d0, float& s1, float& d1) {
        const int  gy  = y0 - KR + j;
        const bool rok = (gy >= 0) && (gy < IMG);
        const bool ok0 = rok && (gx0 >= 0) && (gx0 < IMG);
        const bool ok1 = rok && tail && (gx1 < IMG);
        const long b = (long)gy * IMG;
        const float ax0 = ok0 ? xin[b + gx0] : 0.0f;
        const float ay0 = ok0 ? yin[b + gx0] : 0.0f;
        const float ax1 = ok1 ? xin[b + gx1] : 0.0f;
        const float ay1 = ok1 ? yin[b + gx1] : 0.0f;
        s0 = ax0 + ay0;  d0 = ax0 - ay0;
        s1 = ax1 + ay1;  d1 = ax1 - ay1;
    };

    // 6 distinct packed weights (Gaussian symmetry)
    u64 WW[6];
    #pragma unroll
    for (int k = 0; k < 6; ++k) WW[k] = pk2(W[k], W[k]);
    const u64 NEG1 = pk2(-1.0f, -1.0f);
    const u64 Z64  = 0ull;

    // ring accumulators: packed (mu_s, mu_d) and (E[s^2], E[d^2])
    u64 aMU[11], aSQ[11];
    #pragma unroll
    for (int s = 0; s < 11; ++s) { aMU[s] = Z64; aSQ[s] = Z64; }

    float tsum = 0.0f;

    // preload + stage row 0
    {
        float s0, d0, s1, d1;
        ldrow(0, s0, d0, s1, d1);
        sb[0][t] = make_float2(s0, d0);
        if (tail) sb[0][TW + t] = make_float2(s1, d1);
    }
    __syncthreads();

    for (int jb = 0; jb < NRB; ++jb) {
        #pragma unroll
        for (int u = 0; u < 11; ++u) {
            const int j = jb * 11 + u;

            // prefetch next row (overlaps compute)
            float ns0, nd0, ns1, nd1;
            ldrow(j + 1, ns0, nd0, ns1, nd1);

            // ---- horizontal blur: 3 packed ops per tap ----
            const u64* s = (const u64*)sb[j & 1];
            u64 hmu = Z64, hsq = Z64;
            #pragma unroll
            for (int k = 0; k < KW; ++k) {
                const int kw = (k < 6) ? k : 10 - k;    // literal
                const u64 p  = s[t + k];                // (s, d) LDS.64
                const u64 pp = mul2(p, p);              // (s^2, d^2)
                hmu = fma2(WW[kw], p,  hmu);
                hsq = fma2(WW[kw], pp, hsq);
            }

            // ---- vertical ring update: 2 packed ops per tap ----
            #pragma unroll
            for (int p = 0; p < KW; ++p) {
                const int ss = (u - p + 11) % 11;       // literal
                const int pw = (p < 6) ? p : 10 - p;    // literal
                aMU[ss] = fma2(WW[pw], hmu, aMU[ss]);
                aSQ[ss] = fma2(WW[pw], hsq, aSQ[ss]);
            }

            // ---- finalize output row o = j-10, reset slot ----
            {
                const int so = (u + 1) % 11;
                const int o  = j - (KW - 1);
                if (o >= 0 && o < TH) {
                    const u64 mu  = aMU[so];
                    const u64 mu2 = mul2(mu, mu);             // (mus^2, mud^2)
                    const u64 sg  = fma2(mu2, NEG1, aSQ[so]); // (sig_s, sig_d)
                    float g0, g1, v0, v1;
                    upk2(mu2, g0, g1);
                    upk2(sg,  v0, v1);
                    // 2*mu_xy=(g0-g1)/2 ; mu_x^2+mu_y^2=(g0+g1)/2
                    // 2*sg_xy=(v0-v1)/2 ; sg_x+sg_y    =(v0+v1)/2
                    // scaled x4 on both sides -> TC1/TC2, ratio unchanged.
                    const float num = ((g0 - g1) + TC1) * ((v0 - v1) + TC2);
                    const float den = ((g0 + g1) + TC1) * ((v0 + v1) + TC2);
                    tsum += __fdividef(num, den);
                }
                aMU[so] = Z64; aSQ[so] = Z64;
            }

            // stage prefetched row j+1 into the other buffer (overwrites data
            // last read in iter j-1, fenced by that iteration's barrier)
            const int nb = (j + 1) & 1;
            sb[nb][t] = make_float2(ns0, nd0);
            if (tail) sb[nb][TW + t] = make_float2(ns1, nd1);
            __syncthreads();
        }
    }

    // ---- reduction: warp -> block -> global ----
    #pragma unroll
    for (int off = 16; off > 0; off >>= 1)
        tsum += __shfl_down_sync(0xffffffffu, tsum, off);
    if ((t & 31) == 0) wsum[t >> 5] = tsum;
    __syncthreads();

    if (t == 0) {
        const double bs = (double)wsum[0] + (double)wsum[1]
                        + (double)wsum[2] + (double)wsum[3];
        atomicAdd(&g_sum, bs);
        __threadfence();
        const unsigned r = atomicAdd(&g_cnt, 1u);
        if (r == NBLK - 1u) {
            const double sall = g_sum;
            out[0] = (float)(1.0 - sall / NPIXD);
            g_sum = 0.0;
            __threadfence();
            g_cnt = 0u;
        }
    }
}

extern "C" void kernel_launch(void* const* d_in, const int* in_sizes, int n_in,
                              void* d_out, int out_size)
{
    const float* pred = (const float*)d_in[0];
    const float* targ = (const float*)d_in[1];
    float* out = (float*)d_out;

    dim3 grid(GRIDX, GRIDY, PLANES);   // 4 x 8 x 48 = 1536 blocks
    ssim_kernel<<<grid, NTHREADS>>>(pred, targ, out);
}